// round 15
// baseline (speedup 1.0000x reference)
#include <cuda_runtime.h>

// out[b,o,h,w] = x[b,o,h,w] + bias[o],  bias[o] = -0.1f * sum_{c,kh,kw} |W2[o,c,kh,kw]|
//
// Derivation: adder2d outputs -sum|patch - w| <= 0 everywhere (strictly < 0 for
// continuous random inputs), so relu(adder2d(x, W1)) is exactly 0.0f everywhere.
// adder2d on an all-zero input (zero padding included) yields the per-channel
// constant -sum|W2[o]| at every spatial position. Hence
//   reference(x, W1, W2) == x - 0.1 * sum|W2[o,:,:,:]|.
//
// LSU-issue-floor design: 2048 blocks x 256 threads, 1 float4 payload per thread
// (the proven-best shape). Only WARP 0 of each block computes the |W2[o]| sum
// (6 wide loads/lane + 5 shuffles -> smem); the other 7 warps issue exactly
// 1 LDG.128 (front-batched, in flight across the barrier) + 1 LDS + 1 STG.128.
// This cuts per-block LSU instructions ~40% vs the all-warps-reduce versions.

__global__ __launch_bounds__(256) void fused_resblock_kernel(
    const float* __restrict__ x,
    const float* __restrict__ W2,
    float* __restrict__ out)
{
    __shared__ float s_bias;

    const int t   = threadIdx.x;
    const int bid = blockIdx.x;            // 2048 blocks; 4 per (b,o) slab
    const int i   = bid * 256 + t;         // float4 index into x/out
    const int o   = (bid >> 2) & 63;       // slab = 4096 floats = 1024 float4

    // payload load first: in flight across the barrier wait
    const float4 v = reinterpret_cast<const float4*>(x)[i];

    if (t < 32) {
        // warp 0 only: reduce |W2[o, 0:576]| (2.3 KB, L2/L1-resident)
        const float*  w  = W2 + o * 576;                        // 2304 B, 16B-aligned
        const float4* w4 = reinterpret_cast<const float4*>(w);
        float s = 0.0f;
        #pragma unroll
        for (int k = 0; k < 4; k++) {                           // lanes cover [0,512)
            float4 q = __ldg(w4 + t + k * 32);
            s += fabsf(q.x) + fabsf(q.y) + fabsf(q.z) + fabsf(q.w);
        }
        s += fabsf(__ldg(w + 512 + t)) + fabsf(__ldg(w + 544 + t)); // tail [512,576)
        #pragma unroll
        for (int d = 16; d > 0; d >>= 1)
            s += __shfl_xor_sync(0xFFFFFFFFu, s, d);
        if (t == 0) s_bias = -0.1f * s;
    }
    __syncthreads();

    const float b = s_bias;
    float4 r;
    r.x = v.x + b; r.y = v.y + b; r.z = v.z + b; r.w = v.w + b;
    reinterpret_cast<float4*>(out)[i] = r;
}

extern "C" void kernel_launch(void* const* d_in, const int* in_sizes, int n_in,
                              void* d_out, int out_size) {
    const float* x  = (const float*)d_in[0];   // [8,64,64,64] float32
    // d_in[1] = W1 (unused: relu(adder2d(x, W1)) == 0 exactly)
    const float* W2 = (const float*)d_in[2];   // [64,64,3,3] float32
    float* out = (float*)d_out;

    const int n4 = out_size / 4;               // 524288 float4
    fused_resblock_kernel<<<n4 / 256, 256>>>(x, W2, out);
}